// round 2
// baseline (speedup 1.0000x reference)
#include <cuda_runtime.h>
#include <cstdint>
#include <math.h>

#define N_TOK 16384
#define D     768
#define DC    64
#define KCODES 8192

// ---------------- scratch (device globals: no runtime allocation) ----------------
__device__ float g_H[N_TOK * D];                 // tanh(Z@W1+b1), 48 MB
__device__ float g_Ze[N_TOK * DC];               // normalized encoder output, 4 MB
__device__ unsigned long long g_best[N_TOK];     // packed (mapped_sim<<32)|(8191-idx)
__device__ float g_loss_part[N_TOK / 16];        // per-block loss partials

// monotonic float->uint mapping (total order preserving)
__device__ __forceinline__ unsigned int fmap(float f) {
    unsigned int u = __float_as_uint(f);
    return (u & 0x80000000u) ? ~u : (u | 0x80000000u);
}

// ---------------- kernel 0: zero entire output + g_best ----------------
__global__ void k_zero(float* __restrict__ dout, size_t total) {
    size_t i = (size_t)blockIdx.x * 256 + threadIdx.x;
    size_t n4 = total >> 2;
    if (i < n4) ((float4*)dout)[i] = make_float4(0.f, 0.f, 0.f, 0.f);
    if (i < (total & 3)) dout[(n4 << 2) + i] = 0.f;
    if (i < N_TOK) g_best[i] = 0ull;   // all packed candidates are > 0
}

// ---------------- kernel 1: H = tanh(Z @ W1 + b1) ----------------
// M=16384, N=768, K=768. BM=BN=128, BK=16, 256 threads, 8x8 per thread.
__global__ __launch_bounds__(256) void k_gemm1_tanh(
    const float* __restrict__ A, const float* __restrict__ B,
    const float* __restrict__ bias)
{
    __shared__ float As[16][132];   // [k][m], padded (2-way max conflict)
    __shared__ float Bs[16][128];   // [k][n]
    const int col0 = blockIdx.x * 128;
    const int row0 = blockIdx.y * 128;
    const int tid = threadIdx.x;
    const int tx = tid & 15, ty = tid >> 4;
    float acc[8][8];
    #pragma unroll
    for (int i = 0; i < 8; i++)
        #pragma unroll
        for (int j = 0; j < 8; j++) acc[i][j] = 0.f;

    for (int k0 = 0; k0 < D; k0 += 16) {
        #pragma unroll
        for (int r = 0; r < 2; r++) {             // A tile 128x16
            int f = tid + r * 256;                // 0..511 float4s
            int m = f >> 2;
            int c4 = (f & 3) << 2;
            float4 v = *(const float4*)&A[(size_t)(row0 + m) * D + k0 + c4];
            As[c4 + 0][m] = v.x; As[c4 + 1][m] = v.y;
            As[c4 + 2][m] = v.z; As[c4 + 3][m] = v.w;
        }
        #pragma unroll
        for (int r = 0; r < 2; r++) {             // B tile 16x128
            int f = tid + r * 256;
            int kk = f >> 5;
            int c4 = (f & 31) << 2;
            *(float4*)&Bs[kk][c4] = *(const float4*)&B[(size_t)(k0 + kk) * D + col0 + c4];
        }
        __syncthreads();
        #pragma unroll
        for (int kk = 0; kk < 16; kk++) {
            float a[8], b[8];
            *(float4*)&a[0] = *(float4*)&As[kk][ty * 8];
            *(float4*)&a[4] = *(float4*)&As[kk][ty * 8 + 4];
            *(float4*)&b[0] = *(float4*)&Bs[kk][tx * 8];
            *(float4*)&b[4] = *(float4*)&Bs[kk][tx * 8 + 4];
            #pragma unroll
            for (int i = 0; i < 8; i++)
                #pragma unroll
                for (int j = 0; j < 8; j++)
                    acc[i][j] += a[i] * b[j];
        }
        __syncthreads();
    }
    #pragma unroll
    for (int i = 0; i < 8; i++) {
        int r = row0 + ty * 8 + i;
        #pragma unroll
        for (int j = 0; j < 8; j++)
            acc[i][j] = tanhf(acc[i][j] + bias[col0 + tx * 8 + j]);
        *(float4*)&g_H[(size_t)r * D + col0 + tx * 8]     = *(float4*)&acc[i][0];
        *(float4*)&g_H[(size_t)r * D + col0 + tx * 8 + 4] = *(float4*)&acc[i][4];
    }
}

// ---------------- kernel 2: Ze = l2norm(H @ W2 + b2) ----------------
// 32 tokens per block, 256 threads (8 threads x 8 cols per token).
__global__ __launch_bounds__(256) void k_gemm2_norm(
    const float* __restrict__ W2, const float* __restrict__ b2)
{
    __shared__ float Hs[32][65];
    __shared__ float Ws[64][64];
    const int tok0 = blockIdx.x * 32;
    const int tid = threadIdx.x;
    const int tl = tid >> 3;   // token 0..31
    const int cg = tid & 7;    // col group
    float acc[8];
    #pragma unroll
    for (int j = 0; j < 8; j++) acc[j] = 0.f;

    for (int k0 = 0; k0 < D; k0 += 64) {
        #pragma unroll
        for (int r = 0; r < 4; r++) {              // W2 chunk 64x64
            int f = tid + r * 256;
            int kk = f >> 4, c4 = (f & 15) << 2;
            *(float4*)&Ws[kk][c4] = *(const float4*)&W2[(size_t)(k0 + kk) * DC + c4];
        }
        #pragma unroll
        for (int r = 0; r < 2; r++) {              // H chunk 32x64
            int f = tid + r * 256;
            int m = f >> 4, c4 = (f & 15) << 2;
            float4 v = *(const float4*)&g_H[(size_t)(tok0 + m) * D + k0 + c4];
            Hs[m][c4] = v.x; Hs[m][c4 + 1] = v.y; Hs[m][c4 + 2] = v.z; Hs[m][c4 + 3] = v.w;
        }
        __syncthreads();
        #pragma unroll
        for (int kk = 0; kk < 64; kk++) {
            float h = Hs[tl][kk];
            float b[8];
            *(float4*)&b[0] = *(float4*)&Ws[kk][cg * 8];
            *(float4*)&b[4] = *(float4*)&Ws[kk][cg * 8 + 4];
            #pragma unroll
            for (int j = 0; j < 8; j++) acc[j] += h * b[j];
        }
        __syncthreads();
    }
    float ss = 0.f;
    #pragma unroll
    for (int j = 0; j < 8; j++) { acc[j] += b2[cg * 8 + j]; ss += acc[j] * acc[j]; }
    ss += __shfl_xor_sync(0xffffffffu, ss, 1);
    ss += __shfl_xor_sync(0xffffffffu, ss, 2);
    ss += __shfl_xor_sync(0xffffffffu, ss, 4);
    float inv = 1.0f / fmaxf(sqrtf(ss), 1e-12f);
    #pragma unroll
    for (int j = 0; j < 8; j++) acc[j] *= inv;
    *(float4*)&g_Ze[(size_t)(tok0 + tl) * DC + cg * 8]     = *(float4*)&acc[0];
    *(float4*)&g_Ze[(size_t)(tok0 + tl) * DC + cg * 8 + 4] = *(float4*)&acc[4];
}

// ---------------- kernel 3: sim = Ze @ emb^T, fused argmax ----------------
// Tile: 128 tokens x 128 codes, K=64 resident. 256 threads, 8 tokens x 8 codes each.
// Codes per thread strided by 16 (tx + 16*j) so the es float4 loads are <=2-way.
__global__ __launch_bounds__(256) void k_sim_argmax(const float* __restrict__ E)
{
    extern __shared__ float sm[];
    float* zs = sm;                 // [128][68] row-major tokens
    float* es = sm + 128 * 68;      // [128][68] row-major codes
    const int tok0 = blockIdx.y * 128;
    const int c0 = blockIdx.x * 128;
    const int tid = threadIdx.x;
    const int tx = tid & 15, ty = tid >> 4;

    #pragma unroll
    for (int r = 0; r < 8; r++) {
        int f = tid + 256 * r;        // 0..2047 float4s
        int m = f >> 4;
        int c4 = (f & 15) << 2;
        *(float4*)&zs[m * 68 + c4] = *(const float4*)&g_Ze[(size_t)(tok0 + m) * DC + c4];
        *(float4*)&es[m * 68 + c4] = *(const float4*)&E[(size_t)(c0 + m) * DC + c4];
    }
    __syncthreads();

    float acc[8][8];
    #pragma unroll
    for (int i = 0; i < 8; i++)
        #pragma unroll
        for (int j = 0; j < 8; j++) acc[i][j] = 0.f;

    #pragma unroll 4
    for (int k4 = 0; k4 < 16; k4++) {
        float4 a[8], b[8];
        #pragma unroll
        for (int i = 0; i < 8; i++) a[i] = *(float4*)&zs[(ty * 8 + i) * 68 + k4 * 4];
        #pragma unroll
        for (int j = 0; j < 8; j++) b[j] = *(float4*)&es[(tx + 16 * j) * 68 + k4 * 4];
        #pragma unroll
        for (int i = 0; i < 8; i++)
            #pragma unroll
            for (int j = 0; j < 8; j++)
                acc[i][j] += a[i].x * b[j].x + a[i].y * b[j].y
                           + a[i].z * b[j].z + a[i].w * b[j].w;
    }

    #pragma unroll
    for (int i = 0; i < 8; i++) {
        float bv = acc[i][0];
        int bc = c0 + tx;
        #pragma unroll
        for (int j = 1; j < 8; j++) {              // codes ascending -> ties keep lowest
            int c = c0 + tx + 16 * j;
            if (acc[i][j] > bv) { bv = acc[i][j]; bc = c; }
        }
        unsigned long long p =
            ((unsigned long long)fmap(bv) << 32) | (unsigned int)(KCODES - 1 - bc);
        #pragma unroll
        for (int s = 1; s < 16; s <<= 1) {
            unsigned long long q = __shfl_xor_sync(0xffffffffu, p, s);
            if (q > p) p = q;
        }
        if (tx == 0) atomicMax(&g_best[tok0 + ty * 8 + i], p);
    }
}

// ---------------- kernel 4: scatter one-hot ----------------
__global__ void k_scatter(float* __restrict__ codex)
{
    int t = blockIdx.x * 256 + threadIdx.x;
    if (t < N_TOK) {
        int c = KCODES - 1 - (int)(g_best[t] & 0xffffffffu);
        codex[(size_t)t * KCODES + c] = 1.0f;
    }
}

// ---------------- kernel 5: gather + loss partials + LayerNorm + out = y @ Wp + bp ----
// 16 tokens per block, 128 threads.
__global__ __launch_bounds__(128) void k_ln_gemm3(
    const float* __restrict__ E, const float* __restrict__ gamma,
    const float* __restrict__ beta, const float* __restrict__ Wp,
    const float* __restrict__ bp, float* __restrict__ out)
{
    __shared__ float ys[64][16];
    __shared__ float sds[16];
    const int tok0 = blockIdx.x * 16;
    const int tid = threadIdx.x;
    const int tl = tid >> 3, cg = tid & 7;
    const int t = tok0 + tl;

    int code = KCODES - 1 - (int)(g_best[t] & 0xffffffffu);
    float q[8], z[8];
    *(float4*)&q[0] = *(const float4*)&E[(size_t)code * DC + cg * 8];
    *(float4*)&q[4] = *(const float4*)&E[(size_t)code * DC + cg * 8 + 4];
    *(float4*)&z[0] = *(const float4*)&g_Ze[(size_t)t * DC + cg * 8];
    *(float4*)&z[4] = *(const float4*)&g_Ze[(size_t)t * DC + cg * 8 + 4];

    float s = 0.f, s2 = 0.f, sd = 0.f;
    #pragma unroll
    for (int e = 0; e < 8; e++) {
        s += q[e]; s2 += q[e] * q[e];
        float d = q[e] - z[e]; sd += d * d;
    }
    #pragma unroll
    for (int w = 1; w < 8; w <<= 1) {
        s  += __shfl_xor_sync(0xffffffffu, s,  w);
        s2 += __shfl_xor_sync(0xffffffffu, s2, w);
        sd += __shfl_xor_sync(0xffffffffu, sd, w);
    }
    float mean = s * (1.0f / 64.0f);
    float var  = s2 * (1.0f / 64.0f) - mean * mean;
    float rstd = rsqrtf(var + 1e-5f);
    #pragma unroll
    for (int e = 0; e < 8; e++) {
        int c = cg * 8 + e;
        ys[c][tl] = (q[e] - mean) * rstd * gamma[c] + beta[c];
    }
    if (cg == 0) sds[tl] = sd;
    __syncthreads();
    if (tid == 0) {
        float tot = 0.f;
        #pragma unroll
        for (int i = 0; i < 16; i++) tot += sds[i];
        g_loss_part[blockIdx.x] = tot;
    }

    for (int n = tid; n < D; n += 128) {
        float acc[16];
        #pragma unroll
        for (int i = 0; i < 16; i++) acc[i] = 0.f;
        #pragma unroll 8
        for (int c = 0; c < DC; c++) {
            float w = Wp[(size_t)c * D + n];
            float4 y0 = *(float4*)&ys[c][0];
            float4 y1 = *(float4*)&ys[c][4];
            float4 y2 = *(float4*)&ys[c][8];
            float4 y3 = *(float4*)&ys[c][12];
            acc[0]  += y0.x * w; acc[1]  += y0.y * w; acc[2]  += y0.z * w; acc[3]  += y0.w * w;
            acc[4]  += y1.x * w; acc[5]  += y1.y * w; acc[6]  += y1.z * w; acc[7]  += y1.w * w;
            acc[8]  += y2.x * w; acc[9]  += y2.y * w; acc[10] += y2.z * w; acc[11] += y2.w * w;
            acc[12] += y3.x * w; acc[13] += y3.y * w; acc[14] += y3.z * w; acc[15] += y3.w * w;
        }
        float bb = bp[n];
        #pragma unroll
        for (int i = 0; i < 16; i++)
            out[(size_t)(tok0 + i) * D + n] = acc[i] + bb;
    }
}

// ---------------- kernel 6: deterministic loss reduction ----------------
__global__ void k_loss_reduce(float* __restrict__ loss_out)
{
    __shared__ float red[256];
    int tid = threadIdx.x;
    float s = 0.f;
    for (int i = tid; i < N_TOK / 16; i += 256) s += g_loss_part[i];
    red[tid] = s;
    __syncthreads();
    for (int w = 128; w > 0; w >>= 1) {
        if (tid < w) red[tid] += red[tid + w];
        __syncthreads();
    }
    if (tid == 0) loss_out[0] = red[0] * (1.0f / (float)(N_TOK * DC));
}

// ---------------- launch ----------------
extern "C" void kernel_launch(void* const* d_in, const int* in_sizes, int n_in,
                              void* d_out, int out_size)
{
    const float* Z   = (const float*)d_in[0];
    const float* W1  = (const float*)d_in[1];
    const float* b1  = (const float*)d_in[2];
    const float* W2  = (const float*)d_in[3];
    const float* b2  = (const float*)d_in[4];
    const float* emb = (const float*)d_in[5];
    const float* gam = (const float*)d_in[6];
    const float* bet = (const float*)d_in[7];
    const float* Wp  = (const float*)d_in[8];
    const float* bp  = (const float*)d_in[9];

    float* out   = (float*)d_out;
    float* lossp = out + (size_t)N_TOK * D;         // scalar after out
    float* codex = lossp + 1;                        // one-hot after loss

    (void)in_sizes; (void)n_in; (void)out_size;

    cudaFuncSetAttribute(k_sim_argmax,
                         cudaFuncAttributeMaxDynamicSharedMemorySize, 69632);

    const size_t total = (size_t)N_TOK * D + 1 + (size_t)N_TOK * KCODES;
    const int zero_blocks = (int)((total / 4 + 255) / 256);   // 143360

    k_zero<<<zero_blocks, 256>>>((float*)d_out, total);
    k_gemm1_tanh<<<dim3(D / 128, N_TOK / 128), 256>>>(Z, W1, b1);
    k_gemm2_norm<<<N_TOK / 32, 256>>>(W2, b2);
    k_sim_argmax<<<dim3(KCODES / 128, N_TOK / 128), 256, 69632>>>(emb);
    k_scatter<<<(N_TOK + 255) / 256, 256>>>(codex);
    k_ln_gemm3<<<N_TOK / 16, 128>>>(emb, gam, bet, Wp, bp, out);
    k_loss_reduce<<<1, 256>>>(lossp);
}

// round 4
// speedup vs baseline: 1.0763x; 1.0763x over previous
#include <cuda_runtime.h>
#include <cstdint>
#include <math.h>

#define N_TOK 16384
#define D     768
#define DC    64
#define KCODES 8192

// ---------------- scratch (device globals: no runtime allocation) ----------------
__device__ float g_H[N_TOK * D];                 // tanh(Z@W1+b1), 48 MB
__device__ float g_Ze[N_TOK * DC];               // normalized encoder output, 4 MB
__device__ unsigned long long g_best[N_TOK];     // packed (mapped_sim<<32)|(8191-idx)
__device__ float g_loss_part[N_TOK / 16];        // per-block loss partials

// monotonic float->uint mapping (total order preserving)
__device__ __forceinline__ unsigned int fmap(float f) {
    unsigned int u = __float_as_uint(f);
    return (u & 0x80000000u) ? ~u : (u | 0x80000000u);
}

// ---------------- kernel 1: H = tanh(Z @ W1 + b1)  (+ zero loss+codex & g_best) ---
// M=16384, N=768, K=768. BM=BN=128, BK=16, 256 threads, 8x8 per thread.
// zero4 points at the loss scalar (16B-aligned); region = 1 + N_TOK*KCODES floats.
__global__ __launch_bounds__(256, 2) void k_gemm1_tanh(
    const float* __restrict__ A, const float* __restrict__ B,
    const float* __restrict__ bias, float4* __restrict__ zero4)
{
    __shared__ float As[16][132];   // [k][m], padded
    __shared__ float Bs[16][128];   // [k][n]
    const int col0 = blockIdx.x * 128;
    const int row0 = blockIdx.y * 128;
    const int tid = threadIdx.x;
    const int tx = tid & 15, ty = tid >> 4;

    // ---- fire-and-forget zeroing of loss + one-hot output + g_best ----
    {
        const unsigned int flat = blockIdx.y * gridDim.x + blockIdx.x;   // 0..767
        const float4 z4 = make_float4(0.f, 0.f, 0.f, 0.f);
        const size_t total4 = ((size_t)N_TOK * KCODES + 1) / 4;          // 33554432
        const size_t stride = (size_t)768 * 256;
        for (size_t i = (size_t)flat * 256 + tid; i < total4; i += stride)
            zero4[i] = z4;
        if (flat == 0 && tid == 0)                                        // scalar tail
            ((float*)zero4)[(size_t)N_TOK * KCODES] = 0.f;
        if (flat < 64) g_best[flat * 256 + tid] = 0ull;  // all candidates > 0
    }

    float acc[8][8];
    #pragma unroll
    for (int i = 0; i < 8; i++)
        #pragma unroll
        for (int j = 0; j < 8; j++) acc[i][j] = 0.f;

    for (int k0 = 0; k0 < D; k0 += 16) {
        #pragma unroll
        for (int r = 0; r < 2; r++) {             // A tile 128x16
            int f = tid + r * 256;                // 0..511 float4s
            int m = f >> 2;
            int c4 = (f & 3) << 2;
            float4 v = *(const float4*)&A[(size_t)(row0 + m) * D + k0 + c4];
            As[c4 + 0][m] = v.x; As[c4 + 1][m] = v.y;
            As[c4 + 2][m] = v.z; As[c4 + 3][m] = v.w;
        }
        #pragma unroll
        for (int r = 0; r < 2; r++) {             // B tile 16x128
            int f = tid + r * 256;
            int kk = f >> 5;
            int c4 = (f & 31) << 2;
            *(float4*)&Bs[kk][c4] = *(const float4*)&B[(size_t)(k0 + kk) * D + col0 + c4];
        }
        __syncthreads();
        #pragma unroll
        for (int kk = 0; kk < 16; kk++) {
            float a[8];
            *(float4*)&a[0] = *(float4*)&As[kk][ty * 8];
            *(float4*)&a[4] = *(float4*)&As[kk][ty * 8 + 4];
            #pragma unroll
            for (int j4 = 0; j4 < 2; j4++) {
                float4 b = *(float4*)&Bs[kk][tx * 8 + j4 * 4];
                #pragma unroll
                for (int i = 0; i < 8; i++) {
                    acc[i][j4 * 4 + 0] += a[i] * b.x;
                    acc[i][j4 * 4 + 1] += a[i] * b.y;
                    acc[i][j4 * 4 + 2] += a[i] * b.z;
                    acc[i][j4 * 4 + 3] += a[i] * b.w;
                }
            }
        }
        __syncthreads();
    }
    #pragma unroll
    for (int i = 0; i < 8; i++) {
        int r = row0 + ty * 8 + i;
        #pragma unroll
        for (int j = 0; j < 8; j++)
            acc[i][j] = tanhf(acc[i][j] + bias[col0 + tx * 8 + j]);
        *(float4*)&g_H[(size_t)r * D + col0 + tx * 8]     = *(float4*)&acc[i][0];
        *(float4*)&g_H[(size_t)r * D + col0 + tx * 8 + 4] = *(float4*)&acc[i][4];
    }
}

// ---------------- kernel 2: Ze = l2norm(H @ W2 + b2) ----------------
// 32 tokens per block, 256 threads (8 threads x 8 cols per token).
__global__ __launch_bounds__(256) void k_gemm2_norm(
    const float* __restrict__ W2, const float* __restrict__ b2)
{
    __shared__ float Hs[32][65];
    __shared__ float Ws[64][64];
    const int tok0 = blockIdx.x * 32;
    const int tid = threadIdx.x;
    const int tl = tid >> 3;   // token 0..31
    const int cg = tid & 7;    // col group
    float acc[8];
    #pragma unroll
    for (int j = 0; j < 8; j++) acc[j] = 0.f;

    for (int k0 = 0; k0 < D; k0 += 64) {
        #pragma unroll
        for (int r = 0; r < 4; r++) {              // W2 chunk 64x64
            int f = tid + r * 256;
            int kk = f >> 4, c4 = (f & 15) << 2;
            *(float4*)&Ws[kk][c4] = *(const float4*)&W2[(size_t)(k0 + kk) * DC + c4];
        }
        #pragma unroll
        for (int r = 0; r < 2; r++) {              // H chunk 32x64
            int f = tid + r * 256;
            int m = f >> 4, c4 = (f & 15) << 2;
            float4 v = *(const float4*)&g_H[(size_t)(tok0 + m) * D + k0 + c4];
            Hs[m][c4] = v.x; Hs[m][c4 + 1] = v.y; Hs[m][c4 + 2] = v.z; Hs[m][c4 + 3] = v.w;
        }
        __syncthreads();
        #pragma unroll
        for (int kk = 0; kk < 64; kk++) {
            float h = Hs[tl][kk];
            float b[8];
            *(float4*)&b[0] = *(float4*)&Ws[kk][cg * 8];
            *(float4*)&b[4] = *(float4*)&Ws[kk][cg * 8 + 4];
            #pragma unroll
            for (int j = 0; j < 8; j++) acc[j] += h * b[j];
        }
        __syncthreads();
    }
    float ss = 0.f;
    #pragma unroll
    for (int j = 0; j < 8; j++) { acc[j] += b2[cg * 8 + j]; ss += acc[j] * acc[j]; }
    ss += __shfl_xor_sync(0xffffffffu, ss, 1);
    ss += __shfl_xor_sync(0xffffffffu, ss, 2);
    ss += __shfl_xor_sync(0xffffffffu, ss, 4);
    float inv = 1.0f / fmaxf(sqrtf(ss), 1e-12f);
    #pragma unroll
    for (int j = 0; j < 8; j++) acc[j] *= inv;
    *(float4*)&g_Ze[(size_t)(tok0 + tl) * DC + cg * 8]     = *(float4*)&acc[0];
    *(float4*)&g_Ze[(size_t)(tok0 + tl) * DC + cg * 8 + 4] = *(float4*)&acc[4];
}

// ---------------- kernel 3: sim = Ze @ emb^T, fused argmax ----------------
// Tile: 128 tokens x 128 codes, K=64 resident. 256 threads, 8 tokens x 8 codes each.
// __launch_bounds__(256,2): cap regs at 128 so two blocks co-reside (16 warps/SM).
__global__ __launch_bounds__(256, 2) void k_sim_argmax(const float* __restrict__ E)
{
    extern __shared__ float sm[];
    float* zs = sm;                 // [128][68] row-major tokens
    float* es = sm + 128 * 68;      // [128][68] row-major codes
    const int tok0 = blockIdx.y * 128;
    const int c0 = blockIdx.x * 128;
    const int tid = threadIdx.x;
    const int tx = tid & 15, ty = tid >> 4;

    #pragma unroll
    for (int r = 0; r < 8; r++) {
        int f = tid + 256 * r;        // 0..2047 float4s
        int m = f >> 4;
        int c4 = (f & 15) << 2;
        *(float4*)&zs[m * 68 + c4] = *(const float4*)&g_Ze[(size_t)(tok0 + m) * DC + c4];
        *(float4*)&es[m * 68 + c4] = *(const float4*)&E[(size_t)(c0 + m) * DC + c4];
    }
    __syncthreads();

    float acc[8][8];
    #pragma unroll
    for (int i = 0; i < 8; i++)
        #pragma unroll
        for (int j = 0; j < 8; j++) acc[i][j] = 0.f;

    #pragma unroll 4
    for (int k4 = 0; k4 < 16; k4++) {
        float4 a[8];
        #pragma unroll
        for (int i = 0; i < 8; i++) a[i] = *(float4*)&zs[(ty * 8 + i) * 68 + k4 * 4];
        #pragma unroll
        for (int j = 0; j < 8; j++) {
            float4 b = *(float4*)&es[(tx + 16 * j) * 68 + k4 * 4];
            #pragma unroll
            for (int i = 0; i < 8; i++)
                acc[i][j] += a[i].x * b.x + a[i].y * b.y
                           + a[i].z * b.z + a[i].w * b.w;
        }
    }

    #pragma unroll
    for (int i = 0; i < 8; i++) {
        float bv = acc[i][0];
        int bc = c0 + tx;
        #pragma unroll
        for (int j = 1; j < 8; j++) {              // codes ascending -> ties keep lowest
            int c = c0 + tx + 16 * j;
            if (acc[i][j] > bv) { bv = acc[i][j]; bc = c; }
        }
        unsigned long long p =
            ((unsigned long long)fmap(bv) << 32) | (unsigned int)(KCODES - 1 - bc);
        #pragma unroll
        for (int s = 1; s < 16; s <<= 1) {
            unsigned long long q = __shfl_xor_sync(0xffffffffu, p, s);
            if (q > p) p = q;
        }
        if (tx == 0) atomicMax(&g_best[tok0 + ty * 8 + i], p);
    }
}

// ---------------- kernel 4: scatter one-hot ----------------
__global__ void k_scatter(float* __restrict__ codex)
{
    int t = blockIdx.x * 256 + threadIdx.x;
    if (t < N_TOK) {
        int c = KCODES - 1 - (int)(g_best[t] & 0xffffffffu);
        codex[(size_t)t * KCODES + c] = 1.0f;
    }
}

// ---------------- kernel 5: gather + loss partials + LayerNorm + out = y @ Wp + bp ----
// 16 tokens per block, 128 threads.
__global__ __launch_bounds__(128) void k_ln_gemm3(
    const float* __restrict__ E, const float* __restrict__ gamma,
    const float* __restrict__ beta, const float* __restrict__ Wp,
    const float* __restrict__ bp, float* __restrict__ out)
{
    __shared__ float ys[64][16];
    __shared__ float sds[16];
    const int tok0 = blockIdx.x * 16;
    const int tid = threadIdx.x;
    const int tl = tid >> 3, cg = tid & 7;
    const int t = tok0 + tl;

    int code = KCODES - 1 - (int)(g_best[t] & 0xffffffffu);
    float q[8], z[8];
    *(float4*)&q[0] = *(const float4*)&E[(size_t)code * DC + cg * 8];
    *(float4*)&q[4] = *(const float4*)&E[(size_t)code * DC + cg * 8 + 4];
    *(float4*)&z[0] = *(const float4*)&g_Ze[(size_t)t * DC + cg * 8];
    *(float4*)&z[4] = *(const float4*)&g_Ze[(size_t)t * DC + cg * 8 + 4];

    float s = 0.f, s2 = 0.f, sd = 0.f;
    #pragma unroll
    for (int e = 0; e < 8; e++) {
        s += q[e]; s2 += q[e] * q[e];
        float d = q[e] - z[e]; sd += d * d;
    }
    #pragma unroll
    for (int w = 1; w < 8; w <<= 1) {
        s  += __shfl_xor_sync(0xffffffffu, s,  w);
        s2 += __shfl_xor_sync(0xffffffffu, s2, w);
        sd += __shfl_xor_sync(0xffffffffu, sd, w);
    }
    float mean = s * (1.0f / 64.0f);
    float var  = s2 * (1.0f / 64.0f) - mean * mean;
    float rstd = rsqrtf(var + 1e-5f);
    #pragma unroll
    for (int e = 0; e < 8; e++) {
        int c = cg * 8 + e;
        ys[c][tl] = (q[e] - mean) * rstd * gamma[c] + beta[c];
    }
    if (cg == 0) sds[tl] = sd;
    __syncthreads();
    if (tid == 0) {
        float tot = 0.f;
        #pragma unroll
        for (int i = 0; i < 16; i++) tot += sds[i];
        g_loss_part[blockIdx.x] = tot;
    }

    for (int n = tid; n < D; n += 128) {
        float acc[16];
        #pragma unroll
        for (int i = 0; i < 16; i++) acc[i] = 0.f;
        #pragma unroll 8
        for (int c = 0; c < DC; c++) {
            float w = Wp[(size_t)c * D + n];
            float4 y0 = *(float4*)&ys[c][0];
            float4 y1 = *(float4*)&ys[c][4];
            float4 y2 = *(float4*)&ys[c][8];
            float4 y3 = *(float4*)&ys[c][12];
            acc[0]  += y0.x * w; acc[1]  += y0.y * w; acc[2]  += y0.z * w; acc[3]  += y0.w * w;
            acc[4]  += y1.x * w; acc[5]  += y1.y * w; acc[6]  += y1.z * w; acc[7]  += y1.w * w;
            acc[8]  += y2.x * w; acc[9]  += y2.y * w; acc[10] += y2.z * w; acc[11] += y2.w * w;
            acc[12] += y3.x * w; acc[13] += y3.y * w; acc[14] += y3.z * w; acc[15] += y3.w * w;
        }
        float bb = bp[n];
        #pragma unroll
        for (int i = 0; i < 16; i++)
            out[(size_t)(tok0 + i) * D + n] = acc[i] + bb;
    }
}

// ---------------- kernel 6: deterministic loss reduction ----------------
__global__ void k_loss_reduce(float* __restrict__ loss_out)
{
    __shared__ float red[256];
    int tid = threadIdx.x;
    float s = 0.f;
    for (int i = tid; i < N_TOK / 16; i += 256) s += g_loss_part[i];
    red[tid] = s;
    __syncthreads();
    for (int w = 128; w > 0; w >>= 1) {
        if (tid < w) red[tid] += red[tid + w];
        __syncthreads();
    }
    if (tid == 0) loss_out[0] = red[0] * (1.0f / (float)(N_TOK * DC));
}

// ---------------- launch ----------------
extern "C" void kernel_launch(void* const* d_in, const int* in_sizes, int n_in,
                              void* d_out, int out_size)
{
    const float* Z   = (const float*)d_in[0];
    const float* W1  = (const float*)d_in[1];
    const float* b1  = (const float*)d_in[2];
    const float* W2  = (const float*)d_in[3];
    const float* b2  = (const float*)d_in[4];
    const float* emb = (const float*)d_in[5];
    const float* gam = (const float*)d_in[6];
    const float* bet = (const float*)d_in[7];
    const float* Wp  = (const float*)d_in[8];
    const float* bp  = (const float*)d_in[9];

    float* out   = (float*)d_out;
    float* lossp = out + (size_t)N_TOK * D;         // scalar after out (16B-aligned)
    float* codex = lossp + 1;                        // one-hot after loss

    (void)in_sizes; (void)n_in; (void)out_size;

    cudaFuncSetAttribute(k_sim_argmax,
                         cudaFuncAttributeMaxDynamicSharedMemorySize, 69632);

    k_gemm1_tanh<<<dim3(D / 128, N_TOK / 128), 256>>>(Z, W1, b1, (float4*)lossp);
    k_gemm2_norm<<<N_TOK / 32, 256>>>(W2, b2);
    k_sim_argmax<<<dim3(KCODES / 128, N_TOK / 128), 256, 69632>>>(emb);
    k_scatter<<<(N_TOK + 255) / 256, 256>>>(codex);
    k_ln_gemm3<<<N_TOK / 16, 128>>>(emb, gam, bet, Wp, bp, out);
    k_loss_reduce<<<1, 256>>>(lossp);
}